// round 17
// baseline (speedup 1.0000x reference)
#include <cuda_runtime.h>

// GRU-D on GB300 (sm_103a). Fixed problem sizes:
#define BATCH 1024
#define LTRUE 96
#define LPRED 24
#define LALL  120
#define NF    64
#define HID   128

typedef unsigned long long ull;

// ---------------------------------------------------------------------------
// Packed fp32x2 helpers.
// ---------------------------------------------------------------------------
#define FMA2(acc, a, b) \
    asm("fma.rn.f32x2 %0, %1, %2, %0;" : "+l"(acc) : "l"(a), "l"(b))

__device__ __forceinline__ ull pack_dup(float v) {
    ull r; asm("mov.b64 %0, {%1, %1};" : "=l"(r) : "f"(v)); return r;
}
__device__ __forceinline__ ull pack_pair(float a, float b) {
    ull r; asm("mov.b64 %0, {%1, %2};" : "=l"(r) : "f"(a), "f"(b)); return r;
}
__device__ __forceinline__ void unpack2(ull p, float& a, float& b) {
    asm("mov.b64 {%0, %1}, %2;" : "=f"(a), "=f"(b) : "l"(p));
}
__device__ __forceinline__ ull mul2(ull a, ull b) {
    ull r; asm("mul.rn.f32x2 %0, %1, %2;" : "=l"(r) : "l"(a), "l"(b)); return r;
}
__device__ __forceinline__ ull add2(ull a, ull b) {
    ull r; asm("add.rn.f32x2 %0, %1, %2;" : "=l"(r) : "l"(a), "l"(b)); return r;
}

// ---------------------------------------------------------------------------
// Packed weight tables, [kk*128 + j], kk = k/2 (ALL streamed via LDG; two
// co-resident blocks per SM read identical addresses -> shared L1D):
//   g_WRp/g_WZp/g_WN1p : {w(2kk), c(2kk), w(2kk+1), c(2kk+1)}
//   g_WN2p             : {wN2(2kk), wN2(2kk+1)}
// w = merged recurrent weight, c = input-side col
//   (k<64 -> x_in col k ; k>=64 -> mask col 128+k).
// ---------------------------------------------------------------------------
__device__ float4 g_WRp [64 * 128];
__device__ float4 g_WZp [64 * 128];
__device__ float4 g_WN1p[64 * 128];
__device__ float2 g_WN2p[64 * 128];
__device__ float  g_rep[(size_t)BATCH * LPRED * HID];

// Shared memory layout (float offsets) — 4 rows per block
#define OFF_SH    0          // s_h  [k][4]  512 floats
#define OFF_SIN   512        // s_in [k][4]  512
#define OFF_PART  1024       // ull[4*1152] = 9216 floats (stride 9 per j)
#define OFF_SDT   10240      // dt [r][120]  480
#define OFF_BIAS  10720      // 512
// Projection overlay (after the loop)
#define OFFP_WP   0          // 64*129 = 8256
#define OFFP_BP   8256       // 64
#define OFFP_REP  8320       // 24*128 = 3072 (one row at a time)
#define SMEM_FLOATS 11392
#define SMEM_BYTES (SMEM_FLOATS * 4)    // 45568 B -> 2 blocks/SM = 91 KB

#define PSTRIDE 1152         // per-gate partial stride in ull (128*9)

// ---------------------------------------------------------------------------
__global__ void grud_prep_kernel(const float* __restrict__ W_ih,
                                 const float* __restrict__ W_hh)
{
    int idx = blockIdx.x * blockDim.x + threadIdx.x;
    if (idx >= 64 * 128) return;
    int kk = idx >> 7;
    int j  = idx & 127;
    int k0 = 2 * kk, k1 = 2 * kk + 1;
    int c0 = (k0 < 64) ? k0 : (128 + k0);
    int c1 = (k1 < 64) ? k1 : (128 + k1);

    float4 r4;
    r4.x = W_ih[j * 256 + 64 + k0] + W_hh[j * 128 + k0];
    r4.y = W_ih[j * 256 + c0];
    r4.z = W_ih[j * 256 + 64 + k1] + W_hh[j * 128 + k1];
    r4.w = W_ih[j * 256 + c1];
    g_WRp[idx] = r4;

    float4 z4;
    z4.x = W_ih[(128 + j) * 256 + 64 + k0] + W_hh[(128 + j) * 128 + k0];
    z4.y = W_ih[(128 + j) * 256 + c0];
    z4.z = W_ih[(128 + j) * 256 + 64 + k1] + W_hh[(128 + j) * 128 + k1];
    z4.w = W_ih[(128 + j) * 256 + c1];
    g_WZp[idx] = z4;

    float4 n4;
    n4.x = W_ih[(256 + j) * 256 + 64 + k0];
    n4.y = W_ih[(256 + j) * 256 + c0];
    n4.z = W_ih[(256 + j) * 256 + 64 + k1];
    n4.w = W_ih[(256 + j) * 256 + c1];
    g_WN1p[idx] = n4;

    float2 m2;
    m2.x = W_hh[(256 + j) * 128 + k0];
    m2.y = W_hh[(256 + j) * 128 + k1];
    g_WN2p[idx] = m2;
}

// ---------------------------------------------------------------------------
// Main kernel: 256 blocks x 512 threads, 4 batch rows per block,
// __launch_bounds__(512, 2) -> 2 blocks/SM with INDEPENDENT barrier
// domains (the latency-hiding mechanism this round tests).
// Warp wid: gate g = wid>>2, K-quarter q = wid&3. Lane l covers
// j = l + 32*jj (jj<4). acc[jj][pair] covers 2 row-pairs (4 rows).
// Threads tid<256 own feature slots (rf,nf) and h pairs (jr,pr<2).
// ---------------------------------------------------------------------------
__global__ __launch_bounds__(512, 2)
void grud_main_kernel(const float* __restrict__ tp_pred,
                      const float* __restrict__ X,
                      const float* __restrict__ tp_true,
                      const float* __restrict__ mask,
                      const float* __restrict__ Wh_dec,
                      const float* __restrict__ bh_dec,
                      const float* __restrict__ Wx_dec,
                      const float* __restrict__ bx_dec,
                      const float* __restrict__ b_ih,
                      const float* __restrict__ b_hh,
                      const float* __restrict__ Wp,
                      const float* __restrict__ bp,
                      float* __restrict__ out)
{
    extern __shared__ float smem[];
    float*  s_h   = smem + OFF_SH;
    float*  s_in  = smem + OFF_SIN;
    ull*    s_part = (ull*)(smem + OFF_PART);
    float*  s_dt  = smem + OFF_SDT;
    float*  s_bias = smem + OFF_BIAS;

    const int tid = threadIdx.x;
    const int wid = tid >> 5, l = tid & 31;
    const int g   = wid >> 2, q = wid & 3;
    const int jr  = tid & 127, pr = tid >> 7;   // pr<2 threads own h pairs
    const int b0  = blockIdx.x * 4;

    // ---- biases: s_bias[gate*128 + j] ----
    {
        int bg = tid >> 7, bj = tid & 127;
        float ub;
        if      (bg == 0) ub = b_ih[bj]       + b_hh[bj];
        else if (bg == 1) ub = b_ih[128 + bj] + b_hh[128 + bj];
        else if (bg == 2) ub = b_ih[256 + bj];
        else              ub = b_hh[256 + bj];
        s_bias[bg * 128 + bj] = ub;
    }

    // ---- decay constants for own j (threads tid<256) ----
    float S = 0.0f, bh = 0.0f;
    if (tid < 256) {
        #pragma unroll 8
        for (int n = 0; n < NF; n++) S += Wh_dec[jr * NF + n];
        bh = bh_dec[jr];
    }

    // ---- feature slot (tid<256): one (row, feature) per thread ----
    const int rf = (tid >> 6) & 3;    // 0..3
    const int nf = tid & 63;
    float wxd = 0.0f, bx = 0.0f, mu = 0.0f, xl = 0.0f;
    const float* Xp = X    + (size_t)(b0 + rf) * LTRUE * NF + nf;
    const float* Mp = mask + (size_t)(b0 + rf) * LTRUE * NF + nf;
    if (tid < 256) {
        wxd = Wx_dec[nf * 64 + nf];
        bx  = bx_dec[nf];
        float sum = 0.0f, cnt = (float)LPRED;
        for (int t = 0; t < LTRUE; t++) {
            float m = Mp[t * NF], x = Xp[t * NF];
            sum += x * (1.0f - m);  cnt += 1.0f - m;
        }
        mu = sum / fmaxf(cnt, 1.0f);
        xl = Xp[0];                   // LOCF state
    }

    // ---- dt table (4 rows x 120) ----
    if (tid < 480) {
        int r = tid / LALL, t = tid % LALL;
        int b = b0 + r;
        float d = 0.0f;
        if (t > 0) {
            float a = (t     < LTRUE) ? tp_true[b * LTRUE + t]
                                      : tp_pred[b * LPRED + (t - LTRUE)];
            float p = (t - 1 < LTRUE) ? tp_true[b * LTRUE + (t - 1)]
                                      : tp_pred[b * LPRED + (t - 1 - LTRUE)];
            d = a - p;
        }
        s_dt[r * LALL + t] = d;
    }

    ull h = 0ull;                     // own row pair (tid<256 only)
    __syncthreads();

    for (int t = 0; t < LALL; t++) {
        // ======== phase A (tid<256): feature slot + decay own pair ========
        if (tid < 256) {
            float xv = 0.0f, mv = 0.0f;
            if (t < LTRUE) { xv = Xp[t * NF]; mv = Mp[t * NF]; }
            float d  = s_dt[rf * LALL + t];
            float gx = __expf(-fmaxf(fmaf(d, wxd, bx), 0.0f));
            xl = (mv != 0.0f) ? xl : xv;
            float xh = gx * xl + (1.0f - gx) * mu;
            float xi = mv * xv + (1.0f - mv) * xh;
            s_in[nf * 4 + rf]        = xi;   // x_in -> k = n
            s_in[(64 + nf) * 4 + rf] = mv;   // mask -> k = 64+n

            float d0 = s_dt[(2 * pr    ) * LALL + t];
            float d1 = s_dt[(2 * pr + 1) * LALL + t];
            float gh0 = __expf(-fmaxf(fmaf(d0, S, bh), 0.0f));
            float gh1 = __expf(-fmaxf(fmaf(d1, S, bh), 0.0f));
            h = mul2(h, pack_pair(gh0, gh1));
            *(ull*)(s_h + jr * 4 + 2 * pr) = h;
            if (t >= LTRUE) {
                int tt = t - LTRUE;
                float f0, f1; unpack2(h, f0, f1);
                g_rep[((size_t)(b0 + 2 * pr    ) * LPRED + tt) * HID + jr] = f0;
                g_rep[((size_t)(b0 + 2 * pr + 1) * LPRED + tt) * HID + jr] = f1;
            }
        }
        __syncthreads();   // S1

        // ======== phase B: K-quarter GEMM per warp ========
        {
            ull acc[4][2];
            #pragma unroll
            for (int jj = 0; jj < 4; jj++) { acc[jj][0] = 0ull; acc[jj][1] = 0ull; }

            if (g < 3) {
                const float4* T = (g == 0) ? g_WRp : (g == 1) ? g_WZp : g_WN1p;
                const float4* Tp = T + ((q * 16) << 7) + l;
                #pragma unroll 4
                for (int kk = 0; kk < 16; kk++) {
                    const int k0 = (q * 16 + kk) * 2;
                    ulonglong2 hA = *(const ulonglong2*)(s_h  + k0 * 4);
                    ulonglong2 xA = *(const ulonglong2*)(s_in + k0 * 4);
                    ulonglong2 hB = *(const ulonglong2*)(s_h  + k0 * 4 + 4);
                    ulonglong2 xB = *(const ulonglong2*)(s_in + k0 * 4 + 4);
                    #pragma unroll
                    for (int jj = 0; jj < 4; jj++) {
                        float4 w = __ldg(Tp + kk * 128 + jj * 32);
                        ull w0 = pack_dup(w.x), c0 = pack_dup(w.y);
                        FMA2(acc[jj][0], w0, hA.x); FMA2(acc[jj][1], w0, hA.y);
                        FMA2(acc[jj][0], c0, xA.x); FMA2(acc[jj][1], c0, xA.y);
                        ull w1 = pack_dup(w.z), c1 = pack_dup(w.w);
                        FMA2(acc[jj][0], w1, hB.x); FMA2(acc[jj][1], w1, hB.y);
                        FMA2(acc[jj][0], c1, xB.x); FMA2(acc[jj][1], c1, xB.y);
                    }
                }
            } else {
                const float2* Tp = g_WN2p + ((q * 16) << 7) + l;
                #pragma unroll 4
                for (int kk = 0; kk < 16; kk++) {
                    const int k0 = (q * 16 + kk) * 2;
                    ulonglong2 hA = *(const ulonglong2*)(s_h + k0 * 4);
                    ulonglong2 hB = *(const ulonglong2*)(s_h + k0 * 4 + 4);
                    #pragma unroll
                    for (int jj = 0; jj < 4; jj++) {
                        float2 w = __ldg(Tp + kk * 128 + jj * 32);
                        ull w0 = pack_dup(w.x), w1 = pack_dup(w.y);
                        FMA2(acc[jj][0], w0, hA.x); FMA2(acc[jj][1], w0, hA.y);
                        FMA2(acc[jj][0], w1, hB.x); FMA2(acc[jj][1], w1, hB.y);
                    }
                }
            }
            // partials layout [gate][j][pair*4 + q], stride 9 ull per j
            #pragma unroll
            for (int jj = 0; jj < 4; jj++) {
                int jdx = l + 32 * jj;
                s_part[g * PSTRIDE + jdx * 9 + 0 * 4 + q] = acc[jj][0];
                s_part[g * PSTRIDE + jdx * 9 + 1 * 4 + q] = acc[jj][1];
            }
        }
        __syncthreads();   // S2

        // ======== phase C (tid<256): reduce partials + activation ========
        if (tid < 256) {
            const int base = jr * 9 + pr * 4;
            ull sR = 0ull, sZ = 0ull, sN1 = 0ull, sN2 = 0ull;
            #pragma unroll
            for (int qq = 0; qq < 4; qq++) {
                sR  = add2(sR,  s_part[0 * PSTRIDE + base + qq]);
                sZ  = add2(sZ,  s_part[1 * PSTRIDE + base + qq]);
                sN1 = add2(sN1, s_part[2 * PSTRIDE + base + qq]);
                sN2 = add2(sN2, s_part[3 * PSTRIDE + base + qq]);
            }
            sR  = add2(sR,  pack_dup(s_bias[jr]));
            sZ  = add2(sZ,  pack_dup(s_bias[128 + jr]));
            sN1 = add2(sN1, pack_dup(s_bias[256 + jr]));
            sN2 = add2(sN2, pack_dup(s_bias[384 + jr]));

            float ra, rb, za, zb, n1x, n1y, n2x, n2y, hx, hy;
            unpack2(sR, ra, rb);
            unpack2(sZ, za, zb);
            unpack2(sN1, n1x, n1y);
            unpack2(sN2, n2x, n2y);
            unpack2(h, hx, hy);
            float rg0 = 1.0f / (1.0f + __expf(-ra));
            float rg1 = 1.0f / (1.0f + __expf(-rb));
            float zg0 = 1.0f / (1.0f + __expf(-za));
            float zg1 = 1.0f / (1.0f + __expf(-zb));
            float p0  = fmaf(rg0, n2x, n1x);
            float p1  = fmaf(rg1, n2y, n1y);
            float ng0 = 1.0f - 2.0f / (1.0f + __expf(2.0f * p0));
            float ng1 = 1.0f - 2.0f / (1.0f + __expf(2.0f * p1));
            float h0  = (1.0f - zg0) * ng0 + zg0 * hx;
            float h1  = (1.0f - zg1) * ng1 + zg1 * hy;
            h = pack_pair(h0, h1);
        }
    }

    // ======== fused projection: out = rep @ Wp^T + bp (own 4 rows) ========
    __syncthreads();                  // recurrent loop done; smem reusable
    for (int i = tid; i < 64 * 128; i += 512) {
        int n = i >> 7, jj = i & 127;
        smem[OFFP_WP + n * 129 + jj] = Wp[i];
    }
    if (tid < 64) smem[OFFP_BP + tid] = bp[tid];

    for (int r = 0; r < 4; r++) {
        __syncthreads();              // protect rep area (and Wp on r=0)
        const float* repsrc = g_rep + ((size_t)(b0 + r) * LPRED) * HID;
        for (int i = tid; i < LPRED * HID; i += 512)
            smem[OFFP_REP + i] = __ldg(repsrc + i);
        __syncthreads();
        #pragma unroll
        for (int w2 = 0; w2 < 3; w2++) {
            int o  = tid + 512 * w2;          // 0..1535
            int tp = o >> 6, n = o & 63;
            float acc = smem[OFFP_BP + n];
            const float* rp = smem + OFFP_REP + tp * 128;
            const float* wp = smem + OFFP_WP + n * 129;
            #pragma unroll 8
            for (int jj = 0; jj < 128; jj++)
                acc = fmaf(rp[jj], wp[jj], acc);
            out[((size_t)(b0 + r) * LPRED + tp) * 64 + n] = acc;
        }
    }
}

// ---------------------------------------------------------------------------
extern "C" void kernel_launch(void* const* d_in, const int* in_sizes, int n_in,
                              void* d_out, int out_size)
{
    const float* tp_pred = (const float*)d_in[0];
    const float* X       = (const float*)d_in[1];
    const float* tp_true = (const float*)d_in[2];
    const float* mask    = (const float*)d_in[3];
    const float* Wh_dec  = (const float*)d_in[4];
    const float* bh_dec  = (const float*)d_in[5];
    const float* Wx_dec  = (const float*)d_in[6];
    const float* bx_dec  = (const float*)d_in[7];
    const float* W_ih    = (const float*)d_in[8];
    const float* W_hh    = (const float*)d_in[9];
    const float* b_ih    = (const float*)d_in[10];
    const float* b_hh    = (const float*)d_in[11];
    const float* Wp      = (const float*)d_in[12];
    const float* bp      = (const float*)d_in[13];
    float* out = (float*)d_out;

    cudaFuncSetAttribute(grud_main_kernel,
                         cudaFuncAttributeMaxDynamicSharedMemorySize,
                         SMEM_BYTES);

    grud_prep_kernel<<<32, 256>>>(W_ih, W_hh);
    grud_main_kernel<<<BATCH / 4, 512, SMEM_BYTES>>>(
        tp_pred, X, tp_true, mask,
        Wh_dec, bh_dec, Wx_dec, bx_dec, b_ih, b_hh,
        Wp, bp, out);
}